// round 3
// baseline (speedup 1.0000x reference)
#include <cuda_runtime.h>
#include <cstdint>

#define S_LEN   2048
#define DMODEL  2048
#define NH      16
#define HDIM    128
#define KV_DM   512
#define BQ      64
#define NQT     (S_LEN / BQ)        // 32
#define HEAVY   204
#define RECENT  204
#define SEL     (S_LEN - RECENT)    // 1844
#define MASKW   (S_LEN + 1)         // 2049

__device__ float g_hid[S_LEN * DMODEL];
__device__ float g_qw[DMODEL * DMODEL];
__device__ float g_kw[DMODEL * KV_DM];
__device__ float g_vw[DMODEL * KV_DM];
__device__ float g_ow[DMODEL * DMODEL];
__device__ float g_q[S_LEN * DMODEL];
__device__ float g_k[S_LEN * KV_DM];
__device__ float g_v[S_LEN * KV_DM];
__device__ float g_ctx[S_LEN * DMODEL];
__device__ float g_colpart[NH * NQT * S_LEN];
__device__ float g_rmb[NH * S_LEN * 16];                 // per-128-block row maxima
__device__ float g_scores[(size_t)NH * S_LEN * S_LEN];   // 256 MB scratch

// ---------------------------------------------------------------------------
__device__ __forceinline__ float tf32r(float x) {
    uint32_t u;
    asm("cvt.rna.tf32.f32 %0, %1;" : "=r"(u) : "f"(x));
    return __uint_as_float(u);
}
__device__ __forceinline__ float ex2f(float x) {
    float y;
    asm("ex2.approx.ftz.f32 %0, %1;" : "=f"(y) : "f"(x));
    return y;
}
__device__ __forceinline__ void mma_tf32(float* c, const uint32_t* a, const uint32_t* b) {
    asm volatile(
        "mma.sync.aligned.m16n8k8.row.col.f32.tf32.tf32.f32 "
        "{%0,%1,%2,%3}, {%4,%5,%6,%7}, {%8,%9}, {%0,%1,%2,%3};"
        : "+f"(c[0]), "+f"(c[1]), "+f"(c[2]), "+f"(c[3])
        : "r"(a[0]), "r"(a[1]), "r"(a[2]), "r"(a[3]), "r"(b[0]), "r"(b[1]));
}
__device__ __forceinline__ void cpa16(uint32_t s, const float* g) {
    asm volatile("cp.async.cg.shared.global [%0], [%1], 16;" :: "r"(s), "l"(g));
}
__device__ __forceinline__ void cp_commit() {
    asm volatile("cp.async.commit_group;");
}
template<int N> __device__ __forceinline__ void cp_wait() {
    asm volatile("cp.async.wait_group %0;" :: "n"(N));
}
__device__ __forceinline__ unsigned encf(float x) {
    unsigned b = __float_as_uint(x);
    return (b & 0x80000000u) ? ~b : (b | 0x80000000u);
}
__device__ __forceinline__ float decf(unsigned e) {
    unsigned b = (e & 0x80000000u) ? (e & 0x7FFFFFFFu) : ~e;
    return __uint_as_float(b);
}

__global__ void zero_kernel(float* p, int n) {
    int i = blockIdx.x * 256 + threadIdx.x;
    if (i < n) p[i] = 0.0f;
}
__global__ void round4_kernel(float4* dst, const float4* src, int n4) {
    int i = blockIdx.x * 256 + threadIdx.x;
    if (i < n4) {
        float4 v = src[i];
        dst[i] = make_float4(tf32r(v.x), tf32r(v.y), tf32r(v.z), tf32r(v.w));
    }
}

// ---------------------------------------------------------------------------
// cp.async double-buffered tf32 GEMM. BM=128, BK=16, K=2048, 256 threads.
// Inputs pre-rounded to tf32. blockIdx.z picks (B,bias,C) pair.
// ---------------------------------------------------------------------------
template<int BN, int WM, int WN, bool ROUND, bool HASBIAS>
__global__ __launch_bounds__(256) void gemm_ca(
    const float* __restrict__ A,
    const float* __restrict__ B0, const float* __restrict__ B1,
    const float* __restrict__ bias0, const float* __restrict__ bias1,
    float* __restrict__ C0, float* __restrict__ C1, int N)
{
    constexpr int BM = 128, BK = 16, KD = 2048;
    constexpr int ASS = 20;
    constexpr int BSS = BN + 4;
    constexpr int MI = WM / 16, NJ = WN / 8;
    constexpr int WARPS_M = BM / WM;
    constexpr int NIT = KD / BK;

    __shared__ float As[2][BM * ASS];
    __shared__ float Bs[2][BK * BSS];

    const int tid = threadIdx.x;
    const int lane = tid & 31, w = tid >> 5;
    const int wm0 = (w % WARPS_M) * WM;
    const int wn0 = (w / WARPS_M) * WN;
    const int bm = blockIdx.y * BM;
    const int bn = blockIdx.x * BN;

    const float* Bm  = (blockIdx.z == 0) ? B0 : B1;
    const float* bia = (blockIdx.z == 0) ? bias0 : bias1;
    float* C         = (blockIdx.z == 0) ? C0 : C1;

    // cp.async thread mappings
    const int ara = tid & 127;            // A row
    const int aca = (tid >> 7) * 8;       // A col base (2 float4: +0, +4)
    const uint32_t sA = (uint32_t)__cvta_generic_to_shared(&As[0][0]);
    const uint32_t sB = (uint32_t)__cvta_generic_to_shared(&Bs[0][0]);

    float acc[MI][NJ][4];
#pragma unroll
    for (int mi = 0; mi < MI; mi++)
#pragma unroll
        for (int nj = 0; nj < NJ; nj++)
#pragma unroll
            for (int c = 0; c < 4; c++) acc[mi][nj][c] = 0.0f;

    auto issue = [&](int st, int k0) {
        const float* ga = &A[(size_t)(bm + ara) * KD + k0 + aca];
        uint32_t sa = sA + (uint32_t)((st * BM + ara) * ASS + aca) * 4u;
        cpa16(sa, ga);
        cpa16(sa + 16, ga + 4);
        if (BN == 128) {
            const int rb = tid >> 5;           // 0..7
            const int cb = (tid & 31) * 4;
            const float* gb = &Bm[(size_t)(k0 + rb) * N + bn + cb];
            uint32_t sb = sB + (uint32_t)((st * BK + rb) * BSS + cb) * 4u;
            cpa16(sb, gb);
            cpa16(sb + (uint32_t)(8 * BSS) * 4u, gb + (size_t)8 * N);
        } else {
            const int rb = tid >> 4;           // 0..15
            const int cb = (tid & 15) * 4;
            const float* gb = &Bm[(size_t)(k0 + rb) * N + bn + cb];
            uint32_t sb = sB + (uint32_t)((st * BK + rb) * BSS + cb) * 4u;
            cpa16(sb, gb);
        }
    };

    issue(0, 0);
    cp_commit();

    for (int it = 0; it < NIT; it++) {
        if (it + 1 < NIT) {
            issue((it + 1) & 1, (it + 1) * BK);
            cp_commit();
            cp_wait<1>();
        } else {
            cp_wait<0>();
        }
        __syncthreads();
        const float* as = &As[it & 1][0];
        const float* bs = &Bs[it & 1][0];
#pragma unroll
        for (int ks = 0; ks < 2; ks++) {
            const int kk = ks * 8;
            uint32_t af[MI][4], bf[NJ][2];
#pragma unroll
            for (int mi = 0; mi < MI; mi++) {
                int m0 = wm0 + 16 * mi + (lane >> 2);
                af[mi][0] = __float_as_uint(as[m0 * ASS + kk + (lane & 3)]);
                af[mi][1] = __float_as_uint(as[(m0 + 8) * ASS + kk + (lane & 3)]);
                af[mi][2] = __float_as_uint(as[m0 * ASS + kk + 4 + (lane & 3)]);
                af[mi][3] = __float_as_uint(as[(m0 + 8) * ASS + kk + 4 + (lane & 3)]);
            }
#pragma unroll
            for (int nj = 0; nj < NJ; nj++) {
                int n0 = wn0 + 8 * nj + (lane >> 2);
                bf[nj][0] = __float_as_uint(bs[(kk + (lane & 3)) * BSS + n0]);
                bf[nj][1] = __float_as_uint(bs[(kk + 4 + (lane & 3)) * BSS + n0]);
            }
#pragma unroll
            for (int mi = 0; mi < MI; mi++)
#pragma unroll
                for (int nj = 0; nj < NJ; nj++)
                    mma_tf32(acc[mi][nj], af[mi], bf[nj]);
        }
        __syncthreads();
    }

#pragma unroll
    for (int mi = 0; mi < MI; mi++) {
#pragma unroll
        for (int nj = 0; nj < NJ; nj++) {
            int row = bm + wm0 + 16 * mi + (lane >> 2);
            int col = bn + wn0 + 8 * nj + 2 * (lane & 3);
            float bx = 0.0f, by = 0.0f;
            if (HASBIAS) { bx = bia[col]; by = bia[col + 1]; }
            float v0x = acc[mi][nj][0] + bx, v0y = acc[mi][nj][1] + by;
            float v1x = acc[mi][nj][2] + bx, v1y = acc[mi][nj][3] + by;
            if (ROUND) {
                v0x = tf32r(v0x); v0y = tf32r(v0y);
                v1x = tf32r(v1x); v1y = tf32r(v1y);
            }
            *(float2*)&C[(size_t)row * N + col] = make_float2(v0x, v0y);
            *(float2*)&C[(size_t)(row + 8) * N + col] = make_float2(v1x, v1y);
        }
    }
}

// ---------------------------------------------------------------------------
// Causal scores GEMM + fused per-128-block row maxima.
// ---------------------------------------------------------------------------
__global__ __launch_bounds__(256) void scores_tf32() {
    constexpr int ASS = 36;
    const int nb = blockIdx.x, mb = blockIdx.y, h = blockIdx.z;
    if (nb > mb) return;
    const int kvh = h >> 2;

    __shared__ float Qs[128 * ASS];
    __shared__ float Ks[128 * ASS];
    __shared__ unsigned rmax_sh[128];

    const int tid = threadIdx.x;
    const int lane = tid & 31, w = tid >> 5;
    const int wm0 = (w & 1) * 64;
    const int wn0 = (w >> 1) * 32;
    const int ar = tid >> 3;
    const int ac = (tid & 7) * 4;

    if (tid < 128) rmax_sh[tid] = 0u;

    float acc[4][4][4];
#pragma unroll
    for (int mi = 0; mi < 4; mi++)
#pragma unroll
        for (int nj = 0; nj < 4; nj++)
#pragma unroll
            for (int c = 0; c < 4; c++) acc[mi][nj][c] = 0.0f;

    const float* Qg = g_q + (size_t)(mb * 128) * DMODEL + h * HDIM;
    const float* Kg = g_k + (size_t)(nb * 128) * KV_DM + kvh * HDIM;

    float4 pq[4], pk[4];
#pragma unroll
    for (int i = 0; i < 4; i++) {
        pq[i] = *(const float4*)&Qg[(size_t)(ar + 32 * i) * DMODEL + ac];
        pk[i] = *(const float4*)&Kg[(size_t)(ar + 32 * i) * KV_DM + ac];
    }

    for (int k0 = 0; k0 < HDIM; k0 += 32) {
        __syncthreads();
#pragma unroll
        for (int i = 0; i < 4; i++) {
            *(float4*)&Qs[(ar + 32 * i) * ASS + ac] = pq[i];
            *(float4*)&Ks[(ar + 32 * i) * ASS + ac] = pk[i];
        }
        __syncthreads();
        if (k0 + 32 < HDIM) {
#pragma unroll
            for (int i = 0; i < 4; i++) {
                pq[i] = *(const float4*)&Qg[(size_t)(ar + 32 * i) * DMODEL + k0 + 32 + ac];
                pk[i] = *(const float4*)&Kg[(size_t)(ar + 32 * i) * KV_DM + k0 + 32 + ac];
            }
        }
#pragma unroll
        for (int ks = 0; ks < 4; ks++) {
            const int kk = ks * 8;
            uint32_t af[4][4], bf[4][2];
#pragma unroll
            for (int mi = 0; mi < 4; mi++) {
                int m0 = wm0 + 16 * mi + (lane >> 2);
                af[mi][0] = __float_as_uint(Qs[m0 * ASS + kk + (lane & 3)]);
                af[mi][1] = __float_as_uint(Qs[(m0 + 8) * ASS + kk + (lane & 3)]);
                af[mi][2] = __float_as_uint(Qs[m0 * ASS + kk + 4 + (lane & 3)]);
                af[mi][3] = __float_as_uint(Qs[(m0 + 8) * ASS + kk + 4 + (lane & 3)]);
            }
#pragma unroll
            for (int nj = 0; nj < 4; nj++) {
                int n0 = wn0 + 8 * nj + (lane >> 2);
                bf[nj][0] = __float_as_uint(Ks[n0 * ASS + kk + (lane & 3)]);
                bf[nj][1] = __float_as_uint(Ks[n0 * ASS + kk + 4 + (lane & 3)]);
            }
#pragma unroll
            for (int mi = 0; mi < 4; mi++)
#pragma unroll
                for (int nj = 0; nj < 4; nj++)
                    mma_tf32(acc[mi][nj], af[mi], bf[nj]);
        }
    }

    const float SCL2 = 0.08838834764831845f * 1.4426950408889634f;
    float* sh = g_scores + (size_t)h * S_LEN * S_LEN;
#pragma unroll
    for (int mi = 0; mi < 4; mi++) {
#pragma unroll
        for (int nj = 0; nj < 4; nj++) {
            int row = mb * 128 + wm0 + 16 * mi + (lane >> 2);
            int col = nb * 128 + wn0 + 8 * nj + 2 * (lane & 3);
            float2 v0, v1;
            v0.x = (col     <= row)     ? acc[mi][nj][0] * SCL2 : -1e30f;
            v0.y = (col + 1 <= row)     ? acc[mi][nj][1] * SCL2 : -1e30f;
            v1.x = (col     <= row + 8) ? acc[mi][nj][2] * SCL2 : -1e30f;
            v1.y = (col + 1 <= row + 8) ? acc[mi][nj][3] * SCL2 : -1e30f;
            *(float2*)&sh[(size_t)row * S_LEN + col] = v0;
            *(float2*)&sh[(size_t)(row + 8) * S_LEN + col] = v1;
            int rr = wm0 + 16 * mi + (lane >> 2);
            atomicMax(&rmax_sh[rr],     encf(fmaxf(v0.x, v0.y)));
            atomicMax(&rmax_sh[rr + 8], encf(fmaxf(v1.x, v1.y)));
        }
    }
    __syncthreads();
    if (tid < 128)
        g_rmb[((size_t)h * S_LEN + mb * 128 + tid) * 16 + nb] = decf(rmax_sh[tid]);
}

// ---------------------------------------------------------------------------
// Attention over cached scores: block row-max, l-pass (read-only),
// p-pass (recompute exp) -> colsums + P@V (tf32 mma).
// ---------------------------------------------------------------------------
__global__ __launch_bounds__(256) void attn_kernel() {
    const int qt = blockIdx.x, h = blockIdx.y;
    const int kvh = h >> 2;
    const int tid = threadIdx.x;
    const int lane = tid & 31, w = tid >> 5;
    const int tx = tid & 15, ty = tid >> 4;
    const int r0 = ty * 4, c0 = tx * 4;
    const int qbase = qt * BQ;

    __shared__ float sP[BQ * 68];
    __shared__ float Vs[64 * 72];
    __shared__ float red[BQ * 16];
    __shared__ float m_sh[BQ], inv_sh[BQ];

    float* sh = g_scores + (size_t)h * S_LEN * S_LEN;

    // row max from per-block maxima
    if (tid < BQ) {
        int row = qbase + tid;
        int nbmax = row >> 7;
        const float* rp = &g_rmb[((size_t)h * S_LEN + row) * 16];
        float m = rp[0];
        for (int nb = 1; nb <= nbmax; nb++) m = fmaxf(m, rp[nb]);
        m_sh[tid] = m;
    }
    __syncthreads();

    // l-pass (read-only)
    float mr[4];
#pragma unroll
    for (int i = 0; i < 4; i++) mr[i] = m_sh[r0 + i];
    float ls[4] = {0.f, 0.f, 0.f, 0.f};
    for (int kt = 0; kt <= qt; kt++) {
#pragma unroll
        for (int i = 0; i < 4; i++) {
            float4 v = *(const float4*)&sh[(size_t)(qbase + r0 + i) * S_LEN + kt * 64 + c0];
            ls[i] += (ex2f(v.x - mr[i]) + ex2f(v.y - mr[i])) +
                     (ex2f(v.z - mr[i]) + ex2f(v.w - mr[i]));
        }
    }
#pragma unroll
    for (int i = 0; i < 4; i++) red[(r0 + i) * 16 + tx] = ls[i];
    __syncthreads();
    if (tid < BQ) {
        float l = 0.0f;
#pragma unroll
        for (int j = 0; j < 16; j++) l += red[tid * 16 + j];
        inv_sh[tid] = 1.0f / l;
    }
    __syncthreads();

    // p-pass: colsums + P@V
    const int wm0 = (w & 1) * 32;
    const int wn0 = (w >> 1) * 16;
    float o[2][2][2][4];
#pragma unroll
    for (int a = 0; a < 2; a++)
#pragma unroll
        for (int b = 0; b < 2; b++)
#pragma unroll
            for (int c = 0; c < 2; c++)
#pragma unroll
                for (int d = 0; d < 4; d++) o[a][b][c][d] = 0.0f;
    float il[4];
#pragma unroll
    for (int i = 0; i < 4; i++) il[i] = inv_sh[r0 + i];

    for (int kt = 0; kt <= qt; kt++) {
        float4 pv[4];
#pragma unroll
        for (int i = 0; i < 4; i++) {
            float4 v = *(const float4*)&sh[(size_t)(qbase + r0 + i) * S_LEN + kt * 64 + c0];
            v.x = ex2f(v.x - mr[i]) * il[i];
            v.y = ex2f(v.y - mr[i]) * il[i];
            v.z = ex2f(v.z - mr[i]) * il[i];
            v.w = ex2f(v.w - mr[i]) * il[i];
            pv[i] = v;
        }
        __syncthreads();
#pragma unroll
        for (int i = 0; i < 4; i++)
            *(float4*)&sP[(r0 + i) * 68 + c0] = pv[i];
        __syncthreads();

        if (tid < 64) {
            float cs = 0.0f;
#pragma unroll 8
            for (int q = 0; q < 64; q++) cs += sP[q * 68 + tid];
            g_colpart[((size_t)h * NQT + qt) * S_LEN + kt * 64 + tid] = cs;
        }

#pragma unroll
        for (int hlf = 0; hlf < 2; hlf++) {
            __syncthreads();
            {
                const int key = tid >> 4;
                const int dd = (tid & 15) * 4;
#pragma unroll
                for (int i = 0; i < 4; i++) {
                    float4 v = *(const float4*)&g_v[(size_t)(kt * 64 + key + 16 * i) * KV_DM +
                                                    kvh * HDIM + hlf * 64 + dd];
                    *(float4*)&Vs[(key + 16 * i) * 72 + dd] = v;
                }
            }
            __syncthreads();
#pragma unroll
            for (int ks = 0; ks < 8; ks++) {
                const int kk = ks * 8;
                uint32_t af[2][4], bf[2][2];
#pragma unroll
                for (int mi = 0; mi < 2; mi++) {
                    int m0 = wm0 + 16 * mi + (lane >> 2);
                    af[mi][0] = __float_as_uint(sP[m0 * 68 + kk + (lane & 3)]);
                    af[mi][1] = __float_as_uint(sP[(m0 + 8) * 68 + kk + (lane & 3)]);
                    af[mi][2] = __float_as_uint(sP[m0 * 68 + kk + 4 + (lane & 3)]);
                    af[mi][3] = __float_as_uint(sP[(m0 + 8) * 68 + kk + 4 + (lane & 3)]);
                }
#pragma unroll
                for (int nj = 0; nj < 2; nj++) {
                    int n0 = wn0 + 8 * nj + (lane >> 2);
                    bf[nj][0] = __float_as_uint(Vs[(kk + (lane & 3)) * 72 + n0]);
                    bf[nj][1] = __float_as_uint(Vs[(kk + 4 + (lane & 3)) * 72 + n0]);
                }
#pragma unroll
                for (int mi = 0; mi < 2; mi++)
#pragma unroll
                    for (int nj = 0; nj < 2; nj++)
                        mma_tf32(o[hlf][mi][nj], af[mi], bf[nj]);
            }
        }
    }

#pragma unroll
    for (int hlf = 0; hlf < 2; hlf++)
#pragma unroll
        for (int mi = 0; mi < 2; mi++)
#pragma unroll
            for (int nj = 0; nj < 2; nj++) {
                int row = qbase + wm0 + 16 * mi + (lane >> 2);
                int col = h * HDIM + hlf * 64 + wn0 + 8 * nj + 2 * (lane & 3);
                *(float2*)&g_ctx[(size_t)row * DMODEL + col] =
                    make_float2(tf32r(o[hlf][mi][nj][0]), tf32r(o[hlf][mi][nj][1]));
                *(float2*)&g_ctx[(size_t)(row + 8) * DMODEL + col] =
                    make_float2(tf32r(o[hlf][mi][nj][2]), tf32r(o[hlf][mi][nj][3]));
            }
}

// ---------------------------------------------------------------------------
// Heavy-hitter mask: deterministic iterative argmax (lowest idx on ties).
// ---------------------------------------------------------------------------
__global__ __launch_bounds__(1024) void topk_kernel(float* __restrict__ mask_out) {
    const int h = blockIdx.x;
    const int tid = threadIdx.x;
    __shared__ float vals[SEL];
    __shared__ float wv[32];
    __shared__ int   wi[32];

    for (int i = tid; i < SEL; i += 1024) {
        float s = 0.0f;
        for (int qt = 0; qt < NQT; qt++)
            s += g_colpart[((size_t)h * NQT + qt) * S_LEN + i];
        vals[i] = s;
    }
    float* mrow = mask_out + (size_t)h * MASKW;
    for (int i = tid; i < MASKW; i += 1024)
        mrow[i] = (i >= (MASKW - RECENT)) ? 1.0f : 0.0f;
    __syncthreads();

    for (int it = 0; it < HEAVY; it++) {
        float best = -1.0f;
        int bidx = SEL;
        for (int i = tid; i < SEL; i += 1024) {
            float v = vals[i];
            if (v > best) { best = v; bidx = i; }
        }
#pragma unroll
        for (int off = 16; off > 0; off >>= 1) {
            float ov = __shfl_down_sync(0xFFFFFFFFu, best, off);
            int oi = __shfl_down_sync(0xFFFFFFFFu, bidx, off);
            if (ov > best || (ov == best && oi < bidx)) { best = ov; bidx = oi; }
        }
        if ((tid & 31) == 0) { wv[tid >> 5] = best; wi[tid >> 5] = bidx; }
        __syncthreads();
        if (tid < 32) {
            best = wv[tid]; bidx = wi[tid];
#pragma unroll
            for (int off = 16; off > 0; off >>= 1) {
                float ov = __shfl_down_sync(0xFFFFFFFFu, best, off);
                int oi = __shfl_down_sync(0xFFFFFFFFu, bidx, off);
                if (ov > best || (ov == best && oi < bidx)) { best = ov; bidx = oi; }
            }
            if (tid == 0) { mrow[bidx] = 1.0f; vals[bidx] = -1.0f; }
        }
        __syncthreads();
    }
}

// ---------------------------------------------------------------------------
extern "C" void kernel_launch(void* const* d_in, const int* in_sizes, int n_in,
                              void* d_out, int out_size) {
    (void)in_sizes; (void)n_in; (void)out_size;
    const float* hidden = (const float*)d_in[0];
    const float* q_w = (const float*)d_in[1];
    const float* q_b = (const float*)d_in[2];
    const float* k_w = (const float*)d_in[3];
    const float* k_b = (const float*)d_in[4];
    const float* v_w = (const float*)d_in[5];
    const float* v_b = (const float*)d_in[6];
    const float* o_w = (const float*)d_in[7];
    float* out = (float*)d_out;

    float *ghid, *gqw, *gkw, *gvw, *gow, *gq, *gk, *gv, *gctx, *gcp;
    cudaGetSymbolAddress((void**)&ghid, g_hid);
    cudaGetSymbolAddress((void**)&gqw,  g_qw);
    cudaGetSymbolAddress((void**)&gkw,  g_kw);
    cudaGetSymbolAddress((void**)&gvw,  g_vw);
    cudaGetSymbolAddress((void**)&gow,  g_ow);
    cudaGetSymbolAddress((void**)&gq,   g_q);
    cudaGetSymbolAddress((void**)&gk,   g_k);
    cudaGetSymbolAddress((void**)&gv,   g_v);
    cudaGetSymbolAddress((void**)&gctx, g_ctx);
    cudaGetSymbolAddress((void**)&gcp,  g_colpart);

    // pre-round inputs to tf32
    round4_kernel<<<(S_LEN * DMODEL / 4 + 255) / 256, 256>>>((float4*)ghid, (const float4*)hidden, S_LEN * DMODEL / 4);
    round4_kernel<<<(DMODEL * DMODEL / 4 + 255) / 256, 256>>>((float4*)gqw, (const float4*)q_w, DMODEL * DMODEL / 4);
    round4_kernel<<<(DMODEL * KV_DM / 4 + 255) / 256, 256>>>((float4*)gkw, (const float4*)k_w, DMODEL * KV_DM / 4);
    round4_kernel<<<(DMODEL * KV_DM / 4 + 255) / 256, 256>>>((float4*)gvw, (const float4*)v_w, DMODEL * KV_DM / 4);
    round4_kernel<<<(DMODEL * DMODEL / 4 + 255) / 256, 256>>>((float4*)gow, (const float4*)o_w, DMODEL * DMODEL / 4);

    const int ncp = NH * NQT * S_LEN;
    zero_kernel<<<(ncp + 255) / 256, 256>>>(gcp, ncp);

    // Q projection
    gemm_ca<128, 64, 32, true, true><<<dim3(DMODEL / 128, S_LEN / 128, 1), 256>>>(
        ghid, gqw, nullptr, q_b, nullptr, gq, nullptr, DMODEL);
    // K + V projections fused via z
    gemm_ca<64, 32, 32, true, true><<<dim3(KV_DM / 64, S_LEN / 128, 2), 256>>>(
        ghid, gkw, gvw, k_b, v_b, gk, gv, KV_DM);

    scores_tf32<<<dim3(S_LEN / 128, S_LEN / 128, NH), 256>>>();

    attn_kernel<<<dim3(NQT, NH), 256>>>();

    topk_kernel<<<NH, 1024>>>(out + (size_t)S_LEN * DMODEL);

    // output projection
    gemm_ca<128, 64, 32, false, false><<<dim3(DMODEL / 128, S_LEN / 128, 1), 256>>>(
        gctx, gow, nullptr, nullptr, nullptr, out, nullptr, DMODEL);
}